// round 5
// baseline (speedup 1.0000x reference)
#include <cuda_runtime.h>
#include <cstdint>

#define N_DENSE    64
#define N_SAMPLES  121
#define N_CHANNELS 384
#define BATCH      2048
#define ROW_IN     (N_DENSE * (1 + N_SAMPLES))   // 7808 floats per input row
#define ROW_OUT    (N_CHANNELS * N_SAMPLES)      // 46464 floats per output batch
#define ROW_VEC    (ROW_IN / 4)                  // 1952 float4 per input row
#define ROW_PAD    (ROW_IN + 16)                 // +16 floats slack for straddle reads
#define NTHREADS   512
#define NWARPS     (NTHREADS / 32)
#define GRID       444                           // 148 SMs x 3 CTAs
#define SMEM_DYN   (2 * ROW_PAD * sizeof(float)) // two row buffers

__device__ int g_row_ctr;

__global__ void reset_ctr_kernel() { g_row_ctr = 0; }

__device__ __forceinline__ void cp16(float* dst_smem, const float4* src) {
    uint32_t d = (uint32_t)__cvta_generic_to_shared(dst_smem);
    asm volatile("cp.async.cg.shared.global [%0], [%1], 16;\n" :: "r"(d), "l"(src));
}

// Persistent CTAs, work-stealing over batch rows, double-buffered cp.async
// prefetch of the next row while computing the current one. Compute phase is
// the channel-pure-warp gather (uniform chain walks, coalesced vec4 stores).
__global__ __launch_bounds__(NTHREADS, 3)
void sparse_gather_persist(const float* __restrict__ in,
                           float* __restrict__ out)
{
    extern __shared__ float sbuf[];            // [2][ROW_PAD]
    __shared__ int head[N_CHANNELS];
    __shared__ int nxt[N_DENSE];
    __shared__ int s_next;

    const int t = threadIdx.x;
    const int w = t >> 5;
    const int l = t & 31;

    // ---- grab + prefetch first row ----
    if (t == 0) s_next = atomicAdd(&g_row_ctr, 1);
    __syncthreads();
    int row = s_next;
    int phase = 0;
    if (row < BATCH) {
        const float4* src = reinterpret_cast<const float4*>(in + (size_t)row * ROW_IN);
        #pragma unroll
        for (int i = t; i < ROW_VEC; i += NTHREADS)
            cp16(&sbuf[4 * i], &src[i]);
    }
    asm volatile("cp.async.commit_group;\n" ::: "memory");

    while (row < BATCH) {
        // ---- grab + prefetch the NEXT row into the other buffer ----
        if (t == 0) s_next = atomicAdd(&g_row_ctr, 1);
        __syncthreads();                               // (A) prev compute done, s_next visible
        const int nrow = s_next;
        if (t < N_CHANNELS) head[t] = -1;              // safe: prev compute ended at (A)

        float* cbuf = sbuf + phase * ROW_PAD;
        float* nbuf = sbuf + (phase ^ 1) * ROW_PAD;
        if (nrow < BATCH) {
            const float4* src = reinterpret_cast<const float4*>(in + (size_t)nrow * ROW_IN);
            #pragma unroll
            for (int i = t; i < ROW_VEC; i += NTHREADS)
                cp16(&nbuf[4 * i], &src[i]);
            asm volatile("cp.async.commit_group;\n" ::: "memory");
            asm volatile("cp.async.wait_group 1;\n" ::: "memory");  // current row resident
        } else {
            asm volatile("cp.async.commit_group;\n" ::: "memory");
            asm volatile("cp.async.wait_group 0;\n" ::: "memory");
        }
        __syncthreads();                               // (B) cbuf + head init visible

        // ---- build inverted index from staged idx columns ----
        if (t < N_DENSE) {
            int c = (int)cbuf[t];
            c = max(0, min(N_CHANNELS - 1, c));
            nxt[t] = atomicExch(&head[c], t);
        }
        __syncthreads();                               // (C)

        // ---- channel-pure gather (v4 body) ----
        const float* __restrict__ sdata = cbuf + N_DENSE;
        float4* __restrict__ ovec = reinterpret_cast<float4*>(out + (size_t)row * ROW_OUT);

        int c    = w;
        int base = N_SAMPLES * w;
        #pragma unroll 4
        for (int k = 0; k < N_CHANNELS / NWARPS; k++) {
            const int vfirst = (base + 3) >> 2;
            const int vend   = (base + N_SAMPLES + 3) >> 2;
            const int v      = vfirst + l;
            const bool active = (v < vend);
            const int s0     = (v << 2) - base;
            const int nA     = N_SAMPLES - s0;

            float4 acc = make_float4(0.f, 0.f, 0.f, 0.f);

            int d = head[c];                           // uniform broadcast
            while (d >= 0) {
                const float* g = sdata + d * N_SAMPLES + s0;
                if (nA > 0) acc.x += g[0];
                if (nA > 1) acc.y += g[1];
                if (nA > 2) acc.z += g[2];
                if (nA > 3) acc.w += g[3];
                d = nxt[d];
            }
            if ((base + N_SAMPLES) & 3) {              // straddle into channel c+1
                int d2 = head[c + 1];
                while (d2 >= 0) {
                    const float* g2 = sdata + d2 * N_SAMPLES - nA;
                    if (nA < 2 && nA > -2) acc.y += g2[1];
                    if (nA < 3 && nA > -1) acc.z += g2[2];
                    if (nA < 4 && nA >  0) acc.w += g2[3];
                    d2 = nxt[d2];
                }
            }
            if (active) __stcs(&ovec[v], acc);

            c    += NWARPS;
            base += N_SAMPLES * NWARPS;
        }

        row = nrow;
        phase ^= 1;
    }
}

extern "C" void kernel_launch(void* const* d_in, const int* in_sizes, int n_in,
                              void* d_out, int out_size)
{
    static bool attr_set = false;
    if (!attr_set) {
        cudaFuncSetAttribute(sparse_gather_persist,
                             cudaFuncAttributeMaxDynamicSharedMemorySize, SMEM_DYN);
        attr_set = true;
    }
    const float* in  = (const float*)d_in[0];
    float*       out = (float*)d_out;
    reset_ctr_kernel<<<1, 1>>>();
    sparse_gather_persist<<<GRID, NTHREADS, SMEM_DYN>>>(in, out);
}

// round 6
// speedup vs baseline: 1.1003x; 1.1003x over previous
#include <cuda_runtime.h>
#include <cstdint>

#define N_DENSE    64
#define N_SAMPLES  121
#define N_CHANNELS 384
#define BATCH      2048
#define ROW_IN     (N_DENSE * (1 + N_SAMPLES))   // 7808 floats per input row
#define ROW_OUT    (N_CHANNELS * N_SAMPLES)      // 46464 floats per output batch
#define N_VEC      (ROW_OUT / 4)                 // 11616 float4 per batch row
#define DATA_F     (N_DENSE * N_SAMPLES)         // 7744 floats of sample data
#define NTHREADS   384                           // 12 warps -> 5 CTAs/SM (60/64 warps)

// One CTA per batch element (v3 shape). Flat vec4 mapping with incremental
// (c,s) tracking; straddle vec4s handled by TWO predicated chain walks
// (channels c and c+1) instead of four per-element walks with divisions.
__global__ __launch_bounds__(NTHREADS)
void sparse_input_gather_v6(const float* __restrict__ in,
                            float* __restrict__ out)
{
    __shared__ float sdata[DATA_F + 4];   // staged [64][121]
    __shared__ int   head[N_CHANNELS];
    __shared__ int   nxt[N_DENSE];

    const int b = blockIdx.x;
    const int t = threadIdx.x;

    const float* __restrict__ row  = in + (size_t)b * ROW_IN;
    const float* __restrict__ data = row + N_DENSE;

    // ---- phase 1: stage data + build inverted index ----
    int my_c = -1;
    if (t < N_DENSE) {
        int c = (int)__ldg(&row[t]);
        my_c = max(0, min(N_CHANNELS - 1, c));
    }
    if (t < N_CHANNELS) head[t] = -1;

    {
        const float4* __restrict__ src = reinterpret_cast<const float4*>(data);
        float4* __restrict__ dst = reinterpret_cast<float4*>(sdata);
        #pragma unroll
        for (int i = t; i < DATA_F / 4; i += NTHREADS)   // 1936 vec4
            dst[i] = src[i];
    }
    __syncthreads();
    if (t < N_DENSE)
        nxt[t] = atomicExch(&head[my_c], t);
    __syncthreads();

    // ---- phase 2: gather ----
    float4* __restrict__ ovec = reinterpret_cast<float4*>(out + (size_t)b * ROW_OUT);

    // (c, s) for p = 4t; stride NTHREADS vec4 = 1536 floats = 12*121 + 84
    int c = (4 * t) / N_SAMPLES;
    int s = 4 * t - c * N_SAMPLES;

    #pragma unroll 4
    for (int v = t; v < N_VEC; v += NTHREADS) {
        float4 acc = make_float4(0.f, 0.f, 0.f, 0.f);

        if (s <= N_SAMPLES - 4) {
            // fast path: all 4 samples in channel c
            int d = head[c];
            while (d >= 0) {
                const float* g = sdata + d * N_SAMPLES + s;
                acc.x += g[0];
                acc.y += g[1];
                acc.z += g[2];
                acc.w += g[3];
                d = nxt[d];
            }
        } else {
            // straddle: nA = 121 - s in {1,2,3} samples from c, rest from c+1
            const int nA = N_SAMPLES - s;
            int d = head[c];
            while (d >= 0) {                           // walk A: channel c
                const float* g = sdata + d * N_SAMPLES + s;
                acc.x += g[0];
                if (nA > 1) acc.y += g[1];
                if (nA > 2) acc.z += g[2];
                d = nxt[d];
            }
            int d2 = head[c + 1];
            while (d2 >= 0) {                          // walk B: channel c+1
                const float* g2 = sdata + d2 * N_SAMPLES - nA;  // + j, j in [nA,3]
                if (nA < 2) acc.y += g2[1];
                if (nA < 3) acc.z += g2[2];
                acc.w += g2[3];
                d2 = nxt[d2];
            }
        }
        __stcs(&ovec[v], acc);          // streaming 128-bit store

        // advance (c, s) by 1536 flat elements: c += 12, s += 84, wrap
        s += 84; c += 12;
        if (s >= N_SAMPLES) { s -= N_SAMPLES; c++; }
    }
}

extern "C" void kernel_launch(void* const* d_in, const int* in_sizes, int n_in,
                              void* d_out, int out_size)
{
    const float* in  = (const float*)d_in[0];
    float*       out = (float*)d_out;
    sparse_input_gather_v6<<<BATCH, NTHREADS>>>(in, out);
}